// round 1
// baseline (speedup 1.0000x reference)
#include <cuda_runtime.h>
#include <math.h>

#define TT 1024
#define HH 2880
#define II 2880
#define EE 16
#define KTOP 4
#define NROWS (TT * KTOP)   // 4096 always (every token picks exactly 4 experts)
#define ALPHA 1.702f
#define LIMIT 7.0f

// ---------------- scratch (static device globals; no runtime allocation) ----
__device__ float g_gate[(size_t)NROWS * II];   // gate pre-act, then h after act
__device__ float g_up[(size_t)NROWS * II];     // up pre-act
__device__ float g_dn[(size_t)NROWS * HH];     // weighted down-proj rows
__device__ int   g_offs[EE + 1];
__device__ int   g_pos[NROWS];                 // (t*4+k) -> grouped row index
__device__ int   g_rowtok[NROWS];              // grouped row -> token
__device__ float g_roww[NROWS];                // grouped row -> routing weight
__device__ int   g_tidx[NROWS];                // (t*4+k) -> expert id
__device__ float g_tw[NROWS];                  // (t*4+k) -> weight

// ---------------- helpers ---------------------------------------------------
__device__ __forceinline__ unsigned f2tf(float x) {
    unsigned r;
    asm("cvt.rna.tf32.f32 %0, %1;" : "=r"(r) : "f"(x));
    return r;
}

__device__ __forceinline__ void mma8(float* d, const unsigned* a, const unsigned* b) {
    asm volatile(
        "mma.sync.aligned.m16n8k8.row.col.f32.tf32.tf32.f32 "
        "{%0,%1,%2,%3}, {%4,%5,%6,%7}, {%8,%9}, {%0,%1,%2,%3};"
        : "+f"(d[0]), "+f"(d[1]), "+f"(d[2]), "+f"(d[3])
        : "r"(a[0]), "r"(a[1]), "r"(a[2]), "r"(a[3]), "r"(b[0]), "r"(b[1]));
}

// ---------------- router: fp32 logits, top-4, renormalize -------------------
__global__ void router_kernel(const float* __restrict__ x,
                              const float* __restrict__ rw,
                              const float* __restrict__ rb) {
    int t = blockIdx.x;
    int tid = threadIdx.x;
    float acc[EE];
#pragma unroll
    for (int e = 0; e < EE; e++) acc[e] = 0.f;
    const float* xr = x + (size_t)t * HH;
    for (int h = tid; h < HH; h += 128) {
        float xv = xr[h];
#pragma unroll
        for (int e = 0; e < EE; e++) acc[e] = fmaf(xv, rw[e * HH + h], acc[e]);
    }
#pragma unroll
    for (int e = 0; e < EE; e++) {
#pragma unroll
        for (int o = 16; o > 0; o >>= 1) acc[e] += __shfl_xor_sync(0xffffffffu, acc[e], o);
    }
    __shared__ float sl[4][EE];
    int w = tid >> 5;
    if ((tid & 31) == 0) {
#pragma unroll
        for (int e = 0; e < EE; e++) sl[w][e] = acc[e];
    }
    __syncthreads();
    if (tid == 0) {
        float lg[EE];
        float mx = -1e30f;
#pragma unroll
        for (int e = 0; e < EE; e++) {
            lg[e] = sl[0][e] + sl[1][e] + sl[2][e] + sl[3][e] + rb[e];
            mx = fmaxf(mx, lg[e]);
        }
        float p[EE];
#pragma unroll
        for (int e = 0; e < EE; e++) p[e] = __expf(lg[e] - mx);
        bool used[EE];
#pragma unroll
        for (int e = 0; e < EE; e++) used[e] = false;
        int sel[KTOP]; float pv[KTOP]; float psum = 0.f;
        for (int k = 0; k < KTOP; k++) {
            int best = 0; float bv = -1.f;
            for (int e = 0; e < EE; e++)
                if (!used[e] && p[e] > bv) { bv = p[e]; best = e; }
            used[best] = true; sel[k] = best; pv[k] = bv; psum += bv;
        }
        float inv = 1.f / psum;
        for (int k = 0; k < KTOP; k++) {
            g_tidx[t * 4 + k] = sel[k];
            g_tw[t * 4 + k]   = pv[k] * inv;
        }
    }
}

// ---------------- deterministic counting sort by expert ---------------------
__global__ void group_kernel() {
    __shared__ unsigned char eid[NROWS];
    __shared__ int base[EE];
    int tid = threadIdx.x;
    for (int i = tid; i < NROWS; i += blockDim.x) eid[i] = (unsigned char)g_tidx[i];
    __syncthreads();
    if (tid == 0) {
        int cnt[EE];
        for (int e = 0; e < EE; e++) cnt[e] = 0;
        for (int i = 0; i < NROWS; i++) cnt[eid[i]]++;
        int s = 0;
        for (int e = 0; e < EE; e++) { base[e] = s; g_offs[e] = s; s += cnt[e]; }
        g_offs[EE] = s;   // == NROWS
    }
    __syncthreads();
    if (tid < EE) {
        int cur = base[tid];
        for (int i = 0; i < NROWS; i++) {
            if (eid[i] == (unsigned char)tid) {
                g_pos[i] = cur;
                g_rowtok[cur] = i >> 2;
                g_roww[cur] = g_tw[i];
                cur++;
            }
        }
    }
}

// ---------------- grouped GEMM: tf32 mma.sync, BM=128 BN=96 BK=32 -----------
// MODE 0: gate = gather(x) @ w1^T + b1          -> g_gate
// MODE 1: up   = gather(x) @ w3^T + b3          -> g_up
// MODE 2: dn   = w * (h @ w2^T + b2)            -> g_dn   (h lives in g_gate)
template<int MODE>
__global__ __launch_bounds__(256, 2)
void moe_gemm(const float* __restrict__ X, const float* __restrict__ W,
              const float* __restrict__ Bias) {
    const int e = blockIdx.z;
    const int gbase = g_offs[e];
    const int Me = g_offs[e + 1] - gbase;
    const int m0 = blockIdx.y * 128;
    if (m0 >= Me) return;
    const int n0 = blockIdx.x * 96;

    float* Out = (MODE == 0) ? g_gate : (MODE == 1) ? g_up : g_dn;
    const float* A = (MODE == 2) ? g_gate : X;
    const float* Wb = W + (size_t)e * II * HH;

    __shared__ unsigned As[128 * 36];
    __shared__ unsigned Bs[96 * 36];

    const int tid = threadIdx.x;
    const int lane = tid & 31;
    const int wm = (tid >> 5) >> 2;   // 0..1
    const int wn = (tid >> 5) & 3;    // 0..3

    float acc[4][3][4];
#pragma unroll
    for (int i = 0; i < 4; i++)
#pragma unroll
        for (int j = 0; j < 3; j++)
#pragma unroll
            for (int q = 0; q < 4; q++) acc[i][j][q] = 0.f;

    // per-thread base pointers for the 4 A-slots / 3 B-slots
    const float* aptr[4];
#pragma unroll
    for (int i = 0; i < 4; i++) {
        int f4 = tid + i * 256;
        int row = f4 >> 3, c4 = f4 & 7;
        int r = m0 + row;
        if (r < Me) {
            if (MODE == 2) aptr[i] = A + (size_t)(gbase + r) * II + c4 * 4;
            else {
                int tok = g_rowtok[gbase + r];
                aptr[i] = A + (size_t)tok * HH + c4 * 4;
            }
        } else aptr[i] = nullptr;
    }
    const float* bptr[3];
#pragma unroll
    for (int i = 0; i < 3; i++) {
        int f4 = tid + i * 256;
        int n = f4 >> 3, c4 = f4 & 7;
        bptr[i] = Wb + (size_t)(n0 + n) * HH + c4 * 4;
    }

    float4 ra[4], rb[3];
#pragma unroll
    for (int i = 0; i < 4; i++)
        ra[i] = aptr[i] ? *(const float4*)(aptr[i]) : make_float4(0.f, 0.f, 0.f, 0.f);
#pragma unroll
    for (int i = 0; i < 3; i++) rb[i] = *(const float4*)(bptr[i]);

    const int KT = HH / 32;   // 90
    for (int kt = 0; kt < KT; ++kt) {
#pragma unroll
        for (int i = 0; i < 4; i++) {
            int f4 = tid + i * 256;
            int row = f4 >> 3, c4 = f4 & 7;
            uint4 u = make_uint4(f2tf(ra[i].x), f2tf(ra[i].y), f2tf(ra[i].z), f2tf(ra[i].w));
            *(uint4*)&As[row * 36 + c4 * 4] = u;
        }
#pragma unroll
        for (int i = 0; i < 3; i++) {
            int f4 = tid + i * 256;
            int row = f4 >> 3, c4 = f4 & 7;
            uint4 u = make_uint4(f2tf(rb[i].x), f2tf(rb[i].y), f2tf(rb[i].z), f2tf(rb[i].w));
            *(uint4*)&Bs[row * 36 + c4 * 4] = u;
        }
        __syncthreads();
        if (kt + 1 < KT) {
            int k0 = (kt + 1) * 32;
#pragma unroll
            for (int i = 0; i < 4; i++)
                ra[i] = aptr[i] ? *(const float4*)(aptr[i] + k0) : make_float4(0.f, 0.f, 0.f, 0.f);
#pragma unroll
            for (int i = 0; i < 3; i++) rb[i] = *(const float4*)(bptr[i] + k0);
        }
#pragma unroll
        for (int kk = 0; kk < 32; kk += 8) {
            unsigned af[4][4], bf[3][2];
            int c0 = kk + (lane & 3);
#pragma unroll
            for (int mt = 0; mt < 4; mt++) {
                int r0 = wm * 64 + mt * 16 + (lane >> 2);
                af[mt][0] = As[r0 * 36 + c0];
                af[mt][1] = As[(r0 + 8) * 36 + c0];
                af[mt][2] = As[r0 * 36 + c0 + 4];
                af[mt][3] = As[(r0 + 8) * 36 + c0 + 4];
            }
#pragma unroll
            for (int nt = 0; nt < 3; nt++) {
                int nn = wn * 24 + nt * 8 + (lane >> 2);
                bf[nt][0] = Bs[nn * 36 + c0];
                bf[nt][1] = Bs[nn * 36 + c0 + 4];
            }
#pragma unroll
            for (int mt = 0; mt < 4; mt++)
#pragma unroll
                for (int nt = 0; nt < 3; nt++)
                    mma8(acc[mt][nt], af[mt], bf[nt]);
        }
        __syncthreads();
    }

    // epilogue: bias fused; MODE 2 also folds routing weight
#pragma unroll
    for (int mt = 0; mt < 4; mt++) {
        int rloc0 = wm * 64 + mt * 16 + (lane >> 2);
#pragma unroll
        for (int half = 0; half < 2; half++) {
            int r = m0 + rloc0 + half * 8;
            if (r >= Me) continue;
            size_t orow = (size_t)(gbase + r) * (size_t)((MODE == 2) ? HH : II);
            float w = (MODE == 2) ? g_roww[gbase + r] : 1.f;
#pragma unroll
            for (int nt = 0; nt < 3; nt++) {
                int col = n0 + wn * 24 + nt * 8 + (lane & 3) * 2;
                float v0 = acc[mt][nt][half * 2 + 0] + Bias[e * HH + col];
                float v1 = acc[mt][nt][half * 2 + 1] + Bias[e * HH + col + 1];
                if (MODE == 2) { v0 *= w; v1 *= w; }
                Out[orow + col]     = v0;
                Out[orow + col + 1] = v1;
            }
        }
    }
}

// ---------------- clipped SwiGLU, in place into g_gate ----------------------
__global__ void act_kernel() {
    size_t idx = ((size_t)blockIdx.x * 256 + threadIdx.x) * 4;
    float4 g = *(const float4*)&g_gate[idx];
    float4 u = *(const float4*)&g_up[idx];
    float gv[4] = {g.x, g.y, g.z, g.w};
    float uv[4] = {u.x, u.y, u.z, u.w};
    float r[4];
#pragma unroll
    for (int i = 0; i < 4; i++) {
        float gg = fminf(gv[i], LIMIT);
        float uu = fminf(fmaxf(uv[i], -LIMIT), LIMIT);
        float s = 1.f / (1.f + __expf(-ALPHA * gg));
        r[i] = (uu + 1.f) * (gg * s);
    }
    *(float4*)&g_gate[idx] = make_float4(r[0], r[1], r[2], r[3]);
}

// ---------------- per-token fixed-order combine (deterministic) -------------
__global__ void combine_kernel(float* __restrict__ y) {
    int t = blockIdx.x;
    const float* r0 = g_dn + (size_t)g_pos[t * 4 + 0] * HH;
    const float* r1 = g_dn + (size_t)g_pos[t * 4 + 1] * HH;
    const float* r2 = g_dn + (size_t)g_pos[t * 4 + 2] * HH;
    const float* r3 = g_dn + (size_t)g_pos[t * 4 + 3] * HH;
    float* yo = y + (size_t)t * HH;
    for (int c = threadIdx.x * 4; c < HH; c += 256 * 4) {
        float4 a = *(const float4*)(r0 + c);
        float4 b = *(const float4*)(r1 + c);
        float4 d = *(const float4*)(r2 + c);
        float4 f = *(const float4*)(r3 + c);
        float4 o = make_float4(a.x + b.x + d.x + f.x, a.y + b.y + d.y + f.y,
                               a.z + b.z + d.z + f.z, a.w + b.w + d.w + f.w);
        *(float4*)(yo + c) = o;
    }
}

// ---------------- launch ----------------------------------------------------
extern "C" void kernel_launch(void* const* d_in, const int* in_sizes, int n_in,
                              void* d_out, int out_size) {
    const float* x  = (const float*)d_in[0];
    const float* rw = (const float*)d_in[1];
    const float* rb = (const float*)d_in[2];
    const float* w1 = (const float*)d_in[3];
    const float* b1 = (const float*)d_in[4];
    const float* w3 = (const float*)d_in[5];
    const float* b3 = (const float*)d_in[6];
    const float* w2 = (const float*)d_in[7];
    const float* b2 = (const float*)d_in[8];
    float* y = (float*)d_out;

    router_kernel<<<TT, 128>>>(x, rw, rb);
    group_kernel<<<1, 256>>>();

    dim3 ggrid(HH / 96, 8, EE);          // (30, 8, 16); over-provisioned in M
    moe_gemm<0><<<ggrid, 256>>>(x, w1, b1);
    moe_gemm<1><<<ggrid, 256>>>(x, w3, b3);

    act_kernel<<<(NROWS * II) / (256 * 4), 256>>>();   // 11520 blocks, exact

    moe_gemm<2><<<ggrid, 256>>>(nullptr, w2, b2);

    combine_kernel<<<TT, 256>>>(y);
}